// round 14
// baseline (speedup 1.0000x reference)
#include <cuda_runtime.h>
#include <cuda_fp16.h>
#include <cstdint>
#include <math.h>

#define NROI   2000
#define MPAD   2048
#define C_IN   256
#define KDIM   12544      // 256*7*7
#define FDIM   1024
#define NCLS   81
#define NBOX   324
#define NOUT   405
#define NPADW  512        // padded head output dim
#define NCHK   20         // bn row chunks (50 rows each)

// ---------------- scratch ----------------
__device__ __half g_A1hi[(size_t)MPAD * KDIM];
__device__ __half g_B1hi[(size_t)FDIM * KDIM];
__device__ __half g_A2hi[(size_t)MPAD * FDIM];
__device__ __half g_A3hi[(size_t)MPAD * FDIM];
__device__ __half g_A3lo[(size_t)MPAD * FDIM];
__device__ __half g_B2hi[(size_t)FDIM * FDIM];
__device__ __half g_W3hi[(size_t)NPADW * FDIM];
__device__ __half g_W3lo[(size_t)NPADW * FDIM];
__device__ float g_x1[NROI * FDIM];
__device__ float g_x1b[NROI * FDIM];
__device__ float g_x2[NROI * FDIM];
__device__ float g_x2b[NROI * FDIM];
__device__ float g_h[(size_t)MPAD * NPADW];
__device__ float g_hb[(size_t)MPAD * NPADW];
__device__ float g_mu1[2 * FDIM];
__device__ float g_rstd1[2 * FDIM];
__device__ float g_mu2[2 * FDIM];
__device__ float g_rstd2[2 * FDIM];
__device__ float g_psum[2 * NCHK * FDIM];
__device__ float g_psq[2 * NCHK * FDIM];

// ---------------- helpers ----------------
__device__ __forceinline__ uint32_t smem_u32(const void* p) {
    uint32_t a;
    asm("{ .reg .u64 t; cvta.to.shared.u64 t, %1; cvt.u32.u64 %0, t; }" : "=r"(a) : "l"(p));
    return a;
}
#define CPA(dst, src) \
    asm volatile("cp.async.cg.shared.global [%0], [%1], 16;" :: "r"(dst), "l"(src))
#define CPA_COMMIT() asm volatile("cp.async.commit_group;" ::: "memory")
#define CPA_WAIT1()  asm volatile("cp.async.wait_group 1;" ::: "memory")
#define CPA_WAIT0()  asm volatile("cp.async.wait_group 0;" ::: "memory")

__device__ __forceinline__ void ldm4(uint32_t* r, uint32_t addr) {
    asm volatile("ldmatrix.sync.aligned.m8n8.x4.shared.b16 {%0,%1,%2,%3}, [%4];"
        : "=r"(r[0]), "=r"(r[1]), "=r"(r[2]), "=r"(r[3]) : "r"(addr));
}
__device__ __forceinline__ void mma16816(float* d, const uint32_t* a, const uint32_t* b) {
    asm volatile("mma.sync.aligned.m16n8k16.row.col.f32.f16.f16.f32 "
        "{%0,%1,%2,%3},{%4,%5,%6,%7},{%8,%9},{%0,%1,%2,%3};"
        : "+f"(d[0]), "+f"(d[1]), "+f"(d[2]), "+f"(d[3])
        : "r"(a[0]), "r"(a[1]), "r"(a[2]), "r"(a[3]), "r"(b[0]), "r"(b[1]));
}

// ---------------- kernel 1: pyramid ROI align (separable bilinear) ----------
// Per channel: load 14 rows, y-blend in registers -> 7 rows, stage (7 STS),
// then 32 lanes each produce one output from 2 LDS. Double-buffered strip.
__global__ __launch_bounds__(256) void roi_align_kernel(
    const float* __restrict__ rois,
    const float* __restrict__ p2, const float* __restrict__ p3,
    const float* __restrict__ p4, const float* __restrict__ p5)
{
    __shared__ float sm[8][2][7 * 33];

    int roi  = blockIdx.x;
    int b    = roi / 1000;
    int tid  = threadIdx.x;
    int wid  = tid >> 5, lane = tid & 31;

    const float* r = rois + (size_t)roi * 4;
    float y1 = r[0], x1 = r[1], y2 = r[2], x2 = r[3];
    float hh = y2 - y1, ww = x2 - x1;

    float s   = sqrtf(fmaxf(hh * ww, 1e-12f));
    float lvl = log2f(s / 0.21875f);
    int level = 4 + (int)rintf(lvl);
    level = level < 2 ? 2 : (level > 5 ? 5 : level);

    const float* feat; int H;
    if      (level == 2) { feat = p2; H = 256; }
    else if (level == 3) { feat = p3; H = 128; }
    else if (level == 4) { feat = p4; H = 64;  }
    else                 { feat = p5; H = 32;  }
    float Hm1 = (float)(H - 1);

    float wxv[7], wyv[7];
    int xi0v[7], xi1v[7], yi0v[7], yi1v[7];
#pragma unroll
    for (int p = 0; p < 7; p++) {
        float t  = (float)p * (1.0f / 6.0f);
        float xs = (x1 + ww * t) * Hm1;
        float x0 = floorf(xs);
        wxv[p]  = xs - x0;
        int xi = (int)x0;
        xi0v[p] = min(max(xi, 0), H - 1);
        xi1v[p] = min(max(xi + 1, 0), H - 1);
        float ys = (y1 + hh * t) * Hm1;
        float y0 = floorf(ys);
        wyv[p]  = ys - y0;
        int yi = (int)y0;
        yi0v[p] = min(max(yi, 0), H - 1);
        yi1v[p] = min(max(yi + 1, 0), H - 1);
    }

    int xlo  = xi0v[0];
    int span = xi1v[6] - xlo + 1;

    int idx1 = 32 + lane;
    bool act1 = idx1 < 49;
    int py0 = lane / 7,          px0 = lane - py0 * 7;
    int p1  = act1 ? idx1 : 48;
    int py1 = p1 / 7,            px1 = p1 - py1 * 7;

    float wy0 = wyv[py0], wx0 = wxv[px0];
    float wy1 = wyv[py1], wx1 = wxv[px1];
    int c00 = xi0v[px0] - xlo, c01 = xi1v[px0] - xlo;
    int c10 = xi0v[px1] - xlo, c11 = xi1v[px1] - xlo;
    int s0r = py0 * 33, s1r = py1 * 33;
    int ay00 = yi0v[py0], ay01 = yi1v[py0], ax00 = xi0v[px0], ax01 = xi1v[px0];
    int ay10 = yi0v[py1], ay11 = yi1v[py1], ax10 = xi0v[px1], ax11 = xi1v[px1];

    if (span <= 32) {
        for (int cc = 0; cc < 32; cc++) {
            int c = wid * 32 + cc;
            float* w = sm[wid][cc & 1];
            const float* plane = feat + (size_t)(b * C_IN + c) * H * H;
            size_t obase = (size_t)roi * KDIM + (size_t)c * 49;
#pragma unroll
            for (int py = 0; py < 7; py++) {
                float v0 = 0.f, v1 = 0.f;
                if (lane < span) {
                    v0 = plane[yi0v[py] * H + xlo + lane];
                    v1 = plane[yi1v[py] * H + xlo + lane];
                }
                float wy = wyv[py];
                w[py * 33 + lane] = v0 * (1.f - wy) + v1 * wy;
            }
            __syncwarp();
            {
                float a = w[s0r + c00], bb2 = w[s0r + c01];
                float val = a * (1.f - wx0) + bb2 * wx0;
                g_A1hi[obase + lane] = __float2half_rn(val);
            }
            if (act1) {
                float a = w[s1r + c10], bb2 = w[s1r + c11];
                float val = a * (1.f - wx1) + bb2 * wx1;
                g_A1hi[obase + idx1] = __float2half_rn(val);
            }
        }
    } else {
        // rare wide-ROI path: direct gather, separable blend
        for (int c = wid * 32; c < wid * 32 + 32; c++) {
            const float* plane = feat + (size_t)(b * C_IN + c) * H * H;
            size_t obase = (size_t)roi * KDIM + (size_t)c * 49;
            {
                const float* r0 = plane + ay00 * H;
                const float* r1 = plane + ay01 * H;
                float ra = r0[ax00] * (1.f - wy0) + r1[ax00] * wy0;
                float rb = r0[ax01] * (1.f - wy0) + r1[ax01] * wy0;
                float val = ra * (1.f - wx0) + rb * wx0;
                g_A1hi[obase + lane] = __float2half_rn(val);
            }
            if (act1) {
                const float* r0 = plane + ay10 * H;
                const float* r1 = plane + ay11 * H;
                float ra = r0[ax10] * (1.f - wy1) + r1[ax10] * wy1;
                float rb = r0[ax11] * (1.f - wy1) + r1[ax11] * wy1;
                float val = ra * (1.f - wx1) + rb * wx1;
                g_A1hi[obase + idx1] = __float2half_rn(val);
            }
        }
    }
}

// ---------------- fp32 -> fp16 convert ----------------
__global__ __launch_bounds__(256) void cvt_hi_kernel(
    const float* __restrict__ in, __half* __restrict__ hi, int n4)
{
    int i = blockIdx.x * 256 + threadIdx.x;
    if (i >= n4) return;
    float4 v = ((const float4*)in)[i];
    __half2* H = (__half2*)hi;
    H[i*2]   = __half2(__float2half_rn(v.x), __float2half_rn(v.y));
    H[i*2+1] = __half2(__float2half_rn(v.z), __float2half_rn(v.w));
}

// ---------------- head weights: [logitsW; bboxW] -> W3 hi/lo ----------------
__global__ __launch_bounds__(256) void cvt_headw_kernel(
    const float* __restrict__ Wl, const float* __restrict__ Wb)
{
    int o = blockIdx.x;
    int i = threadIdx.x;
    const float* src = (o < NCLS) ? (Wl + (size_t)o * FDIM)
                                  : (Wb + (size_t)(o - NCLS) * FDIM);
    float4 v = ((const float4*)src)[i];
    __half h0 = __float2half_rn(v.x), h1 = __float2half_rn(v.y);
    __half h2 = __float2half_rn(v.z), h3 = __float2half_rn(v.w);
    size_t base = (size_t)o * FDIM / 2 + i * 2;
    __half2* H = (__half2*)g_W3hi;
    __half2* L = (__half2*)g_W3lo;
    H[base]     = __half2(h0, h1);
    H[base + 1] = __half2(h2, h3);
    L[base]     = __half2(__float2half_rn(v.x - __half2float(h0)),
                          __float2half_rn(v.y - __half2float(h1)));
    L[base + 1] = __half2(__float2half_rn(v.z - __half2float(h2)),
                          __float2half_rn(v.w - __half2float(h3)));
}

// ---------------- unified GEMM: split-K x2, single-pass fp16, 2 CTAs/SM ----
#define ROWB    144
#define TILE_B  18432           // 128 * 144 (BK=64)

__device__ __forceinline__ void issue_stage2(
    const __half* __restrict__ Ah, const __half* __restrict__ Bh,
    int K, int k0, uint32_t sbase, int tid)
{
    const __half* gs[2] = {Ah, Bh};
#pragma unroll
    for (int t = 0; t < 2; t++) {
#pragma unroll
        for (int i = 0; i < 4; i++) {
            int u   = tid + i * 256;
            int row = u >> 3, seg = u & 7;
            const void* g = gs[t] + (size_t)row * K + k0 + seg * 8;
            uint32_t sm   = sbase + t * TILE_B + row * ROWB + seg * 16;
            CPA(sm, g);
        }
    }
}

__global__ __launch_bounds__(256, 2) void hmma_gemm(
    const __half* __restrict__ Ahi, const __half* __restrict__ Bhi,
    const float* __restrict__ bias,
    float* __restrict__ CoA, float* __restrict__ CoB,
    int K, int khalf)
{
    const uint32_t STAGE = 2 * TILE_B;

    extern __shared__ char smem[];
    uint32_t sb = smem_u32(smem);

    int tid  = threadIdx.x;
    int wid  = tid >> 5, lane = tid & 31;
    int wm   = (wid & 3) * 32;
    int wn   = (wid >> 2) * 64;
    int bm   = blockIdx.y * 128;
    int bn   = blockIdx.x * 128;
    int kh   = blockIdx.z;

    const __half* Ah = Ahi + (size_t)bm * K + kh * khalf;
    const __half* Bh = Bhi + (size_t)bn * K + kh * khalf;

    uint32_t offA[2], offB[4];
#pragma unroll
    for (int i = 0; i < 2; i++)
        offA[i] = (wm + i * 16 + (lane & 15)) * ROWB + ((lane >> 4) << 4);
#pragma unroll
    for (int j = 0; j < 4; j++)
        offB[j] = (wn + j * 16 + ((lane >> 4) << 3) + (lane & 7)) * ROWB
                + (((lane >> 3) & 1) << 4);

    float acc[2][8][4];
#pragma unroll
    for (int i = 0; i < 2; i++)
#pragma unroll
        for (int n = 0; n < 8; n++)
#pragma unroll
            for (int q = 0; q < 4; q++) acc[i][n][q] = 0.f;

    const int nch = khalf >> 6;

    issue_stage2(Ah, Bh, K, 0, sb, tid);
    CPA_COMMIT();
    if (nch > 1) {
        issue_stage2(Ah, Bh, K, 64, sb + STAGE, tid);
        CPA_COMMIT();
    }

    for (int k = 0; k < nch; k++) {
        if (k == nch - 1) { CPA_WAIT0(); } else { CPA_WAIT1(); }
        __syncthreads();

        if (k + 2 < nch) {
            issue_stage2(Ah, Bh, K, (k + 2) << 6,
                         sb + ((k + 2) % 3) * STAGE, tid);
            CPA_COMMIT();
        }

        uint32_t stb = sb + (k % 3) * STAGE;
#pragma unroll
        for (int s = 0; s < 4; s++) {
            uint32_t so = s * 32;
            uint32_t ah[2][4], bh[4][4];
#pragma unroll
            for (int i = 0; i < 2; i++)
                ldm4(ah[i], stb + 0 * TILE_B + offA[i] + so);
#pragma unroll
            for (int j = 0; j < 4; j++)
                ldm4(bh[j], stb + 1 * TILE_B + offB[j] + so);
#pragma unroll
            for (int i = 0; i < 2; i++)
#pragma unroll
                for (int nf = 0; nf < 8; nf++)
                    mma16816(acc[i][nf], ah[i], &bh[nf >> 1][(nf & 1) * 2]);
        }
    }

    float* Co = kh ? CoB : CoA;
#pragma unroll
    for (int i = 0; i < 2; i++) {
        int r0 = bm + wm + i * 16 + (lane >> 2);
#pragma unroll
        for (int nf = 0; nf < 8; nf++) {
            int c = bn + wn + nf * 8 + (lane & 3) * 2;
            float b0 = kh ? 0.f : bias[c];
            float b1 = kh ? 0.f : bias[c + 1];
            if (r0 < NROI) {
                Co[(size_t)r0 * FDIM + c]     = acc[i][nf][0] + b0;
                Co[(size_t)r0 * FDIM + c + 1] = acc[i][nf][1] + b1;
            }
            if (r0 + 8 < NROI) {
                Co[(size_t)(r0 + 8) * FDIM + c]     = acc[i][nf][2] + b0;
                Co[(size_t)(r0 + 8) * FDIM + c + 1] = acc[i][nf][3] + b1;
            }
        }
    }
}
#define GSMEM (3 * 2 * TILE_B)    // 110592

// ---------------- head GEMM: 3-pass fp16 (Ah*Wh + Al*Wh + Ah*Wl) -----------
__device__ __forceinline__ void issue_stage4(
    const __half* __restrict__ Ah, const __half* __restrict__ Wh,
    const __half* __restrict__ Al, const __half* __restrict__ Wl,
    int K, int k0, uint32_t sbase, int tid)
{
    const __half* gs[4] = {Ah, Wh, Al, Wl};
#pragma unroll
    for (int t = 0; t < 4; t++) {
#pragma unroll
        for (int i = 0; i < 4; i++) {
            int u   = tid + i * 256;
            int row = u >> 3, seg = u & 7;
            const void* g = gs[t] + (size_t)row * K + k0 + seg * 8;
            uint32_t sm   = sbase + t * TILE_B + row * ROWB + seg * 16;
            CPA(sm, g);
        }
    }
}

__global__ __launch_bounds__(256, 1) void hmma_head(
    float* __restrict__ CoA, float* __restrict__ CoB)
{
    const int K = FDIM;
    const int khalf = FDIM / 2;
    const uint32_t STAGE = 4 * TILE_B;

    extern __shared__ char smem[];
    uint32_t sb = smem_u32(smem);

    int tid  = threadIdx.x;
    int wid  = tid >> 5, lane = tid & 31;
    int wm   = (wid & 3) * 32;
    int wn   = (wid >> 2) * 64;
    int bm   = blockIdx.y * 128;
    int bn   = blockIdx.x * 128;
    int kh   = blockIdx.z;

    const __half* Ah = g_A3hi + (size_t)bm * K + kh * khalf;
    const __half* Al = g_A3lo + (size_t)bm * K + kh * khalf;
    const __half* Wh = g_W3hi + (size_t)bn * K + kh * khalf;
    const __half* Wl = g_W3lo + (size_t)bn * K + kh * khalf;

    uint32_t offA[2], offB[4];
#pragma unroll
    for (int i = 0; i < 2; i++)
        offA[i] = (wm + i * 16 + (lane & 15)) * ROWB + ((lane >> 4) << 4);
#pragma unroll
    for (int j = 0; j < 4; j++)
        offB[j] = (wn + j * 16 + ((lane >> 4) << 3) + (lane & 7)) * ROWB
                + (((lane >> 3) & 1) << 4);

    float acc[2][8][4];
#pragma unroll
    for (int i = 0; i < 2; i++)
#pragma unroll
        for (int n = 0; n < 8; n++)
#pragma unroll
            for (int q = 0; q < 4; q++) acc[i][n][q] = 0.f;

    const int nch = khalf >> 6;   // 8

    issue_stage4(Ah, Wh, Al, Wl, K, 0, sb, tid);
    CPA_COMMIT();
    issue_stage4(Ah, Wh, Al, Wl, K, 64, sb + STAGE, tid);
    CPA_COMMIT();

    for (int k = 0; k < nch; k++) {
        if (k == nch - 1) { CPA_WAIT0(); } else { CPA_WAIT1(); }
        __syncthreads();

        if (k + 2 < nch) {
            issue_stage4(Ah, Wh, Al, Wl, K, (k + 2) << 6,
                         sb + ((k + 2) % 3) * STAGE, tid);
            CPA_COMMIT();
        }

        uint32_t stb = sb + (k % 3) * STAGE;
#pragma unroll
        for (int s = 0; s < 4; s++) {
            uint32_t so = s * 32;
            uint32_t ah[2][4], al[2][4], wh4[4][4], wl4[4][4];
#pragma unroll
            for (int i = 0; i < 2; i++) {
                ldm4(ah[i], stb + 0 * TILE_B + offA[i] + so);
                ldm4(al[i], stb + 2 * TILE_B + offA[i] + so);
            }
#pragma unroll
            for (int j = 0; j < 4; j++) {
                ldm4(wh4[j], stb + 1 * TILE_B + offB[j] + so);
                ldm4(wl4[j], stb + 3 * TILE_B + offB[j] + so);
            }
#pragma unroll
            for (int i = 0; i < 2; i++) {
#pragma unroll
                for (int nf = 0; nf < 8; nf++) {
                    const uint32_t* bph = &wh4[nf >> 1][(nf & 1) * 2];
                    const uint32_t* bpl = &wl4[nf >> 1][(nf & 1) * 2];
                    mma16816(acc[i][nf], ah[i], bph);
                    mma16816(acc[i][nf], al[i], bph);
                    mma16816(acc[i][nf], ah[i], bpl);
                }
            }
        }
    }

    float* Co = kh ? CoB : CoA;
#pragma unroll
    for (int i = 0; i < 2; i++) {
        int r0 = bm + wm + i * 16 + (lane >> 2);
#pragma unroll
        for (int nf = 0; nf < 8; nf++) {
            int c = bn + wn + nf * 8 + (lane & 3) * 2;
            if (r0 < NROI) {
                Co[(size_t)r0 * NPADW + c]     = acc[i][nf][0];
                Co[(size_t)r0 * NPADW + c + 1] = acc[i][nf][1];
            }
            if (r0 + 8 < NROI) {
                Co[(size_t)(r0 + 8) * NPADW + c]     = acc[i][nf][2];
                Co[(size_t)(r0 + 8) * NPADW + c + 1] = acc[i][nf][3];
            }
        }
    }
}
#define GSMEM4 (3 * 4 * TILE_B)    // 221184

// ---------------- BN stats: 20 chunks x 50 rows ----------------
__global__ __launch_bounds__(256) void bn_partial_kernel(int phase)
{
    int f  = blockIdx.x * 256 + threadIdx.x;
    int rc = blockIdx.y;
    int b  = blockIdx.z;
    size_t base = ((size_t)b * 1000 + rc * 50) * FDIM + f;

    const float* pa = (phase == 0 ? g_x1 : g_x2) + base;
    const float* pb = (phase == 0 ? g_x1b : g_x2b) + base;

    float s = 0.f, q = 0.f;
#pragma unroll 5
    for (int n = 0; n < 50; n++) {
        float v = pa[(size_t)n * FDIM] + pb[(size_t)n * FDIM];
        s += v; q += v * v;
    }
    int idx = (b * NCHK + rc) * FDIM + f;
    g_psum[idx] = s;
    g_psq[idx]  = q;
}

__global__ __launch_bounds__(256) void bn_final_kernel(int phase)
{
    float* mu   = (phase == 0) ? g_mu1   : g_mu2;
    float* rstd = (phase == 0) ? g_rstd1 : g_rstd2;
    int f = blockIdx.y * 256 + threadIdx.x;
    int b = blockIdx.x;

    float s = 0.f, q = 0.f;
#pragma unroll
    for (int rc = 0; rc < NCHK; rc++) {
        int idx = (b * NCHK + rc) * FDIM + f;
        s += g_psum[idx];
        q += g_psq[idx];
    }
    float m   = s * (1.0f / 1000.0f);
    float var = q * (1.0f / 1000.0f) - m * m;
    mu[b * FDIM + f]   = m;
    rstd[b * FDIM + f] = rsqrtf(var + 1e-5f);
}

// ---------------- BN+relu apply -> fp16 (hi [, lo]) ----------------
template<bool WRITE_LO>
__global__ __launch_bounds__(256) void bn_apply_kernel(
    const float* __restrict__ gam, const float* __restrict__ bet,
    const float* __restrict__ xa, const float* __restrict__ xb,
    const float* __restrict__ mu, const float* __restrict__ rstd,
    __half* __restrict__ hi, __half* __restrict__ lo)
{
    int i = blockIdx.x * 256 + threadIdx.x;
    if (i >= NROI * FDIM / 4) return;
    int e   = i * 4;
    int row = e >> 10;
    int b   = (row >= 1000);
    int kg  = e & 1023;

    float4 va  = *(const float4*)(xa + e);
    float4 vb  = *(const float4*)(xb + e);
    float4 g4  = *(const float4*)(gam + kg);
    float4 b4  = *(const float4*)(bet + kg);
    float4 mu4 = *(const float4*)(mu + b * FDIM + kg);
    float4 rs4 = *(const float4*)(rstd + b * FDIM + kg);
    float v0 = va.x + vb.x, v1 = va.y + vb.y, v2 = va.z + vb.z, v3 = va.w + vb.w;
    float o0 = fmaxf(g4.x * (v0 - mu4.x) * rs4.x + b4.x, 0.f);
    float o1 = fmaxf(g4.y * (v1 - mu4.y) * rs4.y + b4.y, 0.f);
    float o2 = fmaxf(g4.z * (v2 - mu4.z) * rs4.z + b4.z, 0.f);
    float o3 = fmaxf(g4.w * (v3 - mu4.w) * rs4.w + b4.w, 0.f);

    __half h0 = __float2half_rn(o0), h1 = __float2half_rn(o1);
    __half h2 = __float2half_rn(o2), h3 = __float2half_rn(o3);
    __half2* H = (__half2*)hi;
    H[i*2]   = __half2(h0, h1);
    H[i*2+1] = __half2(h2, h3);
    if (WRITE_LO) {
        __half2* L = (__half2*)lo;
        L[i*2]   = __half2(__float2half_rn(o0 - __half2float(h0)),
                           __float2half_rn(o1 - __half2float(h1)));
        L[i*2+1] = __half2(__float2half_rn(o2 - __half2float(h2)),
                           __float2half_rn(o3 - __half2float(h3)));
    }
}

// ---------------- finalize: bias + outputs + softmax ----------------
__global__ __launch_bounds__(256) void finalize_kernel(
    const float* __restrict__ bl, const float* __restrict__ bb,
    float* __restrict__ out)
{
    int tid  = threadIdx.x;
    int wid  = tid >> 5, lane = tid & 31;
    int m    = blockIdx.x * 8 + wid;

    const float* ha = g_h  + (size_t)m * NPADW;
    const float* hb = g_hb + (size_t)m * NPADW;

    float lgv[3] = {-1e30f, -1e30f, -1e30f};
    for (int i = lane, j = 0; i < NOUT; i += 32, j++) {
        float v = ha[i] + hb[i] + ((i < NCLS) ? bl[i] : bb[i - NCLS]);
        if (i < NCLS) {
            out[(size_t)m * NCLS + i] = v;
            lgv[j] = v;
        } else {
            out[324000 + (size_t)m * NBOX + (i - NCLS)] = v;
        }
    }

    float mx = fmaxf(lgv[0], fmaxf(lgv[1], lgv[2]));
#pragma unroll
    for (int off = 16; off; off >>= 1) mx = fmaxf(mx, __shfl_xor_sync(0xffffffffu, mx, off));
    float sum = 0.f;
#pragma unroll
    for (int j = 0; j < 3; j++)
        if (lgv[j] > -1e29f) sum += expf(lgv[j] - mx);
#pragma unroll
    for (int off = 16; off; off >>= 1) sum += __shfl_xor_sync(0xffffffffu, sum, off);
    float inv = 1.0f / sum;
#pragma unroll
    for (int j = 0; j < 3; j++) {
        int i = lane + j * 32;
        if (i < NCLS)
            out[162000 + (size_t)m * NCLS + i] = expf(lgv[j] - mx) * inv;
    }
}

// ---------------- launch ----------------
extern "C" void kernel_launch(void* const* d_in, const int* in_sizes, int n_in,
                              void* d_out, int out_size)
{
    const float* rois    = (const float*)d_in[0];
    const float* p2      = (const float*)d_in[1];
    const float* p3      = (const float*)d_in[2];
    const float* p4      = (const float*)d_in[3];
    const float* p5      = (const float*)d_in[4];
    const float* conv1_w = (const float*)d_in[5];
    const float* conv1_b = (const float*)d_in[6];
    const float* bn1_g   = (const float*)d_in[7];
    const float* bn1_b   = (const float*)d_in[8];
    const float* conv2_w = (const float*)d_in[9];
    const float* conv2_b = (const float*)d_in[10];
    const float* bn2_g   = (const float*)d_in[11];
    const float* bn2_b   = (const float*)d_in[12];
    const float* logitsW = (const float*)d_in[13];
    const float* logitsB = (const float*)d_in[14];
    const float* bboxW   = (const float*)d_in[15];
    const float* bboxB   = (const float*)d_in[16];
    float* out = (float*)d_out;

    cudaFuncSetAttribute(hmma_gemm, cudaFuncAttributeMaxDynamicSharedMemorySize, GSMEM);
    cudaFuncSetAttribute(hmma_head, cudaFuncAttributeMaxDynamicSharedMemorySize, GSMEM4);

    __half *a1h, *b1h, *a2h, *b2h, *a3h, *a3l;
    float *x1, *x1b, *x2, *x2b, *hA, *hB;
    float *mu1, *rs1, *mu2, *rs2;
    cudaGetSymbolAddress((void**)&a1h, g_A1hi);
    cudaGetSymbolAddress((void**)&b1h, g_B1hi);
    cudaGetSymbolAddress((void**)&a2h, g_A2hi);
    cudaGetSymbolAddress((void**)&b2h, g_B2hi);
    cudaGetSymbolAddress((void**)&a3h, g_A3hi);
    cudaGetSymbolAddress((void**)&a3l, g_A3lo);
    cudaGetSymbolAddress((void**)&x1, g_x1);    cudaGetSymbolAddress((void**)&x1b, g_x1b);
    cudaGetSymbolAddress((void**)&x2, g_x2);    cudaGetSymbolAddress((void**)&x2b, g_x2b);
    cudaGetSymbolAddress((void**)&hA, g_h);     cudaGetSymbolAddress((void**)&hB, g_hb);
    cudaGetSymbolAddress((void**)&mu1, g_mu1);  cudaGetSymbolAddress((void**)&rs1, g_rstd1);
    cudaGetSymbolAddress((void**)&mu2, g_mu2);  cudaGetSymbolAddress((void**)&rs2, g_rstd2);

    const int n4_1 = FDIM * KDIM / 4;
    const int n4_2 = FDIM * FDIM / 4;
    const int napp = NROI * FDIM / 4;

    // prep
    cvt_hi_kernel<<<(n4_1 + 255) / 256, 256>>>(conv1_w, b1h, n4_1);
    cvt_hi_kernel<<<(n4_2 + 255) / 256, 256>>>(conv2_w, b2h, n4_2);
    cvt_headw_kernel<<<NOUT, 256>>>(logitsW, bboxW);

    // launch 4: ROI align (separable bilinear) — ncu capture slot
    roi_align_kernel<<<NROI, 256>>>(rois, p2, p3, p4, p5);

    // GEMM1 (split-K x2, single-pass, 2 CTAs/SM)
    hmma_gemm<<<dim3(FDIM / 128, MPAD / 128, 2), 256, GSMEM>>>(
        a1h, b1h, conv1_b, x1, x1b, KDIM, KDIM / 2);

    // BN1
    bn_partial_kernel<<<dim3(4, NCHK, 2), 256>>>(0);
    bn_final_kernel<<<dim3(2, 4), 256>>>(0);
    bn_apply_kernel<false><<<(napp + 255) / 256, 256>>>(
        bn1_g, bn1_b, x1, x1b, mu1, rs1, a2h, nullptr);

    // GEMM2 (single-pass fp16, split-K x2)
    hmma_gemm<<<dim3(FDIM / 128, MPAD / 128, 2), 256, GSMEM>>>(
        a2h, b2h, conv2_b, x2, x2b, FDIM, FDIM / 2);

    // BN2 + apply -> A3 hi/lo
    bn_partial_kernel<<<dim3(4, NCHK, 2), 256>>>(1);
    bn_final_kernel<<<dim3(2, 4), 256>>>(1);
    bn_apply_kernel<true><<<(napp + 255) / 256, 256>>>(
        bn2_g, bn2_b, x2, x2b, mu2, rs2, a3h, a3l);

    // head GEMM (3-pass fp16, split-K x2) + finalize
    hmma_head<<<dim3(NPADW / 128, MPAD / 128, 2), 256, GSMEM4>>>(hA, hB);
    finalize_kernel<<<NROI / 8, 256>>>(logitsB, bboxB, out);
}

// round 15
// speedup vs baseline: 1.0809x; 1.0809x over previous
#include <cuda_runtime.h>
#include <cuda_fp16.h>
#include <cstdint>
#include <math.h>

#define NROI   2000
#define MPAD   2048
#define C_IN   256
#define KDIM   12544      // 256*7*7
#define FDIM   1024
#define NCLS   81
#define NBOX   324
#define NOUT   405
#define NPADW  512        // padded head output dim
#define NCHK   20         // bn row chunks (50 rows each)

// ---------------- scratch ----------------
__device__ __half g_A1hi[(size_t)MPAD * KDIM];
__device__ __half g_B1hi[(size_t)FDIM * KDIM];
__device__ __half g_A2hi[(size_t)MPAD * FDIM];
__device__ __half g_A3hi[(size_t)MPAD * FDIM];
__device__ __half g_A3lo[(size_t)MPAD * FDIM];
__device__ __half g_B2hi[(size_t)FDIM * FDIM];
__device__ __half g_W3hi[(size_t)NPADW * FDIM];
__device__ __half g_W3lo[(size_t)NPADW * FDIM];
__device__ float g_x1[NROI * FDIM];
__device__ float g_x1b[NROI * FDIM];
__device__ float g_x2[NROI * FDIM];
__device__ float g_x2b[NROI * FDIM];
__device__ float g_h[(size_t)MPAD * NPADW];
__device__ float g_hb[(size_t)MPAD * NPADW];
__device__ float g_mu1[2 * FDIM];
__device__ float g_rstd1[2 * FDIM];
__device__ float g_mu2[2 * FDIM];
__device__ float g_rstd2[2 * FDIM];
__device__ float g_psum[2 * NCHK * FDIM];
__device__ float g_psq[2 * NCHK * FDIM];

// ---------------- helpers ----------------
__device__ __forceinline__ uint32_t smem_u32(const void* p) {
    uint32_t a;
    asm("{ .reg .u64 t; cvta.to.shared.u64 t, %1; cvt.u32.u64 %0, t; }" : "=r"(a) : "l"(p));
    return a;
}
#define CPA(dst, src) \
    asm volatile("cp.async.cg.shared.global [%0], [%1], 16;" :: "r"(dst), "l"(src))
#define CPA_COMMIT() asm volatile("cp.async.commit_group;" ::: "memory")
#define CPA_WAIT1()  asm volatile("cp.async.wait_group 1;" ::: "memory")
#define CPA_WAIT0()  asm volatile("cp.async.wait_group 0;" ::: "memory")

__device__ __forceinline__ void ldm4(uint32_t* r, uint32_t addr) {
    asm volatile("ldmatrix.sync.aligned.m8n8.x4.shared.b16 {%0,%1,%2,%3}, [%4];"
        : "=r"(r[0]), "=r"(r[1]), "=r"(r[2]), "=r"(r[3]) : "r"(addr));
}
__device__ __forceinline__ void mma16816(float* d, const uint32_t* a, const uint32_t* b) {
    asm volatile("mma.sync.aligned.m16n8k16.row.col.f32.f16.f16.f32 "
        "{%0,%1,%2,%3},{%4,%5,%6,%7},{%8,%9},{%0,%1,%2,%3};"
        : "+f"(d[0]), "+f"(d[1]), "+f"(d[2]), "+f"(d[3])
        : "r"(a[0]), "r"(a[1]), "r"(a[2]), "r"(a[3]), "r"(b[0]), "r"(b[1]));
}

// ---------------- kernel 1: pyramid ROI align (R13 proven version) ----------
__global__ __launch_bounds__(256) void roi_align_kernel(
    const float* __restrict__ rois,
    const float* __restrict__ p2, const float* __restrict__ p3,
    const float* __restrict__ p4, const float* __restrict__ p5)
{
    __shared__ float sm[8][14 * 33];

    int roi  = blockIdx.x;
    int b    = roi / 1000;
    int tid  = threadIdx.x;
    int wid  = tid >> 5, lane = tid & 31;
    float* w = sm[wid];

    const float* r = rois + (size_t)roi * 4;
    float y1 = r[0], x1 = r[1], y2 = r[2], x2 = r[3];
    float hh = y2 - y1, ww = x2 - x1;

    float s   = sqrtf(fmaxf(hh * ww, 1e-12f));
    float lvl = log2f(s / 0.21875f);
    int level = 4 + (int)rintf(lvl);
    level = level < 2 ? 2 : (level > 5 ? 5 : level);

    const float* feat; int H;
    if      (level == 2) { feat = p2; H = 256; }
    else if (level == 3) { feat = p3; H = 128; }
    else if (level == 4) { feat = p4; H = 64;  }
    else                 { feat = p5; H = 32;  }
    float Hm1 = (float)(H - 1);

    float wxv[7], wyv[7];
    int xi0v[7], xi1v[7], yi0v[7], yi1v[7];
#pragma unroll
    for (int p = 0; p < 7; p++) {
        float t  = (float)p * (1.0f / 6.0f);
        float xs = (x1 + ww * t) * Hm1;
        float x0 = floorf(xs);
        wxv[p]  = xs - x0;
        int xi = (int)x0;
        xi0v[p] = min(max(xi, 0), H - 1);
        xi1v[p] = min(max(xi + 1, 0), H - 1);
        float ys = (y1 + hh * t) * Hm1;
        float y0 = floorf(ys);
        wyv[p]  = ys - y0;
        int yi = (int)y0;
        yi0v[p] = min(max(yi, 0), H - 1);
        yi1v[p] = min(max(yi + 1, 0), H - 1);
    }

    int xlo  = xi0v[0];
    int span = xi1v[6] - xlo + 1;

    int idx1 = 32 + lane;
    bool act1 = idx1 < 49;
    int py0 = lane / 7,          px0 = lane - py0 * 7;
    int p1  = act1 ? idx1 : 48;
    int py1 = p1 / 7,            px1 = p1 - py1 * 7;

    float wy0 = wyv[py0], wx0 = wxv[px0];
    float wy1 = wyv[py1], wx1 = wxv[px1];
    int c00 = xi0v[px0] - xlo, c01 = xi1v[px0] - xlo;
    int c10 = xi0v[px1] - xlo, c11 = xi1v[px1] - xlo;
    int s0a = (2 * py0) * 33,  s0b = s0a + 33;
    int s1a = (2 * py1) * 33,  s1b = s1a + 33;
    int ay00 = yi0v[py0], ay01 = yi1v[py0], ax00 = xi0v[px0], ax01 = xi1v[px0];
    int ay10 = yi0v[py1], ay11 = yi1v[py1], ax10 = xi0v[px1], ax11 = xi1v[px1];

    if (span <= 32) {
        for (int c = wid * 32; c < wid * 32 + 32; c++) {
            const float* plane = feat + (size_t)(b * C_IN + c) * H * H;
            size_t obase = (size_t)roi * KDIM + (size_t)c * 49;
#pragma unroll
            for (int py = 0; py < 7; py++) {
                float v0 = 0.f, v1 = 0.f;
                if (lane < span) {
                    v0 = plane[yi0v[py] * H + xlo + lane];
                    v1 = plane[yi1v[py] * H + xlo + lane];
                }
                w[(2 * py) * 33 + lane]     = v0;
                w[(2 * py + 1) * 33 + lane] = v1;
            }
            __syncwarp();
            {
                float v00 = w[s0a + c00], v01 = w[s0a + c01];
                float v10 = w[s0b + c00], v11 = w[s0b + c01];
                float val = v00 * (1.f - wy0) * (1.f - wx0)
                          + v01 * (1.f - wy0) * wx0
                          + v10 * wy0 * (1.f - wx0)
                          + v11 * wy0 * wx0;
                g_A1hi[obase + lane] = __float2half_rn(val);
            }
            if (act1) {
                float v00 = w[s1a + c10], v01 = w[s1a + c11];
                float v10 = w[s1b + c10], v11 = w[s1b + c11];
                float val = v00 * (1.f - wy1) * (1.f - wx1)
                          + v01 * (1.f - wy1) * wx1
                          + v10 * wy1 * (1.f - wx1)
                          + v11 * wy1 * wx1;
                g_A1hi[obase + idx1] = __float2half_rn(val);
            }
            __syncwarp();
        }
    } else {
        for (int c = wid * 32; c < wid * 32 + 32; c++) {
            const float* plane = feat + (size_t)(b * C_IN + c) * H * H;
            size_t obase = (size_t)roi * KDIM + (size_t)c * 49;
            {
                const float* r0 = plane + ay00 * H;
                const float* r1 = plane + ay01 * H;
                float v00 = r0[ax00], v01 = r0[ax01];
                float v10 = r1[ax00], v11 = r1[ax01];
                float val = v00 * (1.f - wy0) * (1.f - wx0)
                          + v01 * (1.f - wy0) * wx0
                          + v10 * wy0 * (1.f - wx0)
                          + v11 * wy0 * wx0;
                g_A1hi[obase + lane] = __float2half_rn(val);
            }
            if (act1) {
                const float* r0 = plane + ay10 * H;
                const float* r1 = plane + ay11 * H;
                float v00 = r0[ax10], v01 = r0[ax11];
                float v10 = r1[ax10], v11 = r1[ax11];
                float val = v00 * (1.f - wy1) * (1.f - wx1)
                          + v01 * (1.f - wy1) * wx1
                          + v10 * wy1 * (1.f - wx1)
                          + v11 * wy1 * wx1;
                g_A1hi[obase + idx1] = __float2half_rn(val);
            }
        }
    }
}

// ---------------- fp32 -> fp16 convert ----------------
__global__ __launch_bounds__(256) void cvt_hi_kernel(
    const float* __restrict__ in, __half* __restrict__ hi, int n4)
{
    int i = blockIdx.x * 256 + threadIdx.x;
    if (i >= n4) return;
    float4 v = ((const float4*)in)[i];
    __half2* H = (__half2*)hi;
    H[i*2]   = __half2(__float2half_rn(v.x), __float2half_rn(v.y));
    H[i*2+1] = __half2(__float2half_rn(v.z), __float2half_rn(v.w));
}

// ---------------- head weights: [logitsW; bboxW] -> W3 hi/lo ----------------
__global__ __launch_bounds__(256) void cvt_headw_kernel(
    const float* __restrict__ Wl, const float* __restrict__ Wb)
{
    int o = blockIdx.x;
    int i = threadIdx.x;
    const float* src = (o < NCLS) ? (Wl + (size_t)o * FDIM)
                                  : (Wb + (size_t)(o - NCLS) * FDIM);
    float4 v = ((const float4*)src)[i];
    __half h0 = __float2half_rn(v.x), h1 = __float2half_rn(v.y);
    __half h2 = __float2half_rn(v.z), h3 = __float2half_rn(v.w);
    size_t base = (size_t)o * FDIM / 2 + i * 2;
    __half2* H = (__half2*)g_W3hi;
    __half2* L = (__half2*)g_W3lo;
    H[base]     = __half2(h0, h1);
    H[base + 1] = __half2(h2, h3);
    L[base]     = __half2(__float2half_rn(v.x - __half2float(h0)),
                          __float2half_rn(v.y - __half2float(h1)));
    L[base + 1] = __half2(__float2half_rn(v.z - __half2float(h2)),
                          __float2half_rn(v.w - __half2float(h3)));
}

// ---------------- unified GEMM: split-K x2, single-pass fp16, 2 CTAs/SM ----
#define ROWB    144
#define TILE_B  18432           // 128 * 144 (BK=64)

__device__ __forceinline__ void issue_stage2(
    const __half* __restrict__ Ah, const __half* __restrict__ Bh,
    int K, int k0, uint32_t sbase, int tid)
{
    const __half* gs[2] = {Ah, Bh};
#pragma unroll
    for (int t = 0; t < 2; t++) {
#pragma unroll
        for (int i = 0; i < 4; i++) {
            int u   = tid + i * 256;
            int row = u >> 3, seg = u & 7;
            const void* g = gs[t] + (size_t)row * K + k0 + seg * 8;
            uint32_t sm   = sbase + t * TILE_B + row * ROWB + seg * 16;
            CPA(sm, g);
        }
    }
}

__global__ __launch_bounds__(256, 2) void hmma_gemm(
    const __half* __restrict__ Ahi, const __half* __restrict__ Bhi,
    const float* __restrict__ bias,
    float* __restrict__ CoA, float* __restrict__ CoB,
    int K, int khalf)
{
    const uint32_t STAGE = 2 * TILE_B;

    extern __shared__ char smem[];
    uint32_t sb = smem_u32(smem);

    int tid  = threadIdx.x;
    int wid  = tid >> 5, lane = tid & 31;
    int wm   = (wid & 3) * 32;
    int wn   = (wid >> 2) * 64;
    int bm   = blockIdx.y * 128;
    int bn   = blockIdx.x * 128;
    int kh   = blockIdx.z;

    const __half* Ah = Ahi + (size_t)bm * K + kh * khalf;
    const __half* Bh = Bhi + (size_t)bn * K + kh * khalf;

    uint32_t offA[2], offB[4];
#pragma unroll
    for (int i = 0; i < 2; i++)
        offA[i] = (wm + i * 16 + (lane & 15)) * ROWB + ((lane >> 4) << 4);
#pragma unroll
    for (int j = 0; j < 4; j++)
        offB[j] = (wn + j * 16 + ((lane >> 4) << 3) + (lane & 7)) * ROWB
                + (((lane >> 3) & 1) << 4);

    float acc[2][8][4];
#pragma unroll
    for (int i = 0; i < 2; i++)
#pragma unroll
        for (int n = 0; n < 8; n++)
#pragma unroll
            for (int q = 0; q < 4; q++) acc[i][n][q] = 0.f;

    const int nch = khalf >> 6;

    issue_stage2(Ah, Bh, K, 0, sb, tid);
    CPA_COMMIT();
    if (nch > 1) {
        issue_stage2(Ah, Bh, K, 64, sb + STAGE, tid);
        CPA_COMMIT();
    }

    for (int k = 0; k < nch; k++) {
        if (k == nch - 1) { CPA_WAIT0(); } else { CPA_WAIT1(); }
        __syncthreads();

        if (k + 2 < nch) {
            issue_stage2(Ah, Bh, K, (k + 2) << 6,
                         sb + ((k + 2) % 3) * STAGE, tid);
            CPA_COMMIT();
        }

        uint32_t stb = sb + (k % 3) * STAGE;
#pragma unroll
        for (int s = 0; s < 4; s++) {
            uint32_t so = s * 32;
            uint32_t ah[2][4], bh[4][4];
#pragma unroll
            for (int i = 0; i < 2; i++)
                ldm4(ah[i], stb + 0 * TILE_B + offA[i] + so);
#pragma unroll
            for (int j = 0; j < 4; j++)
                ldm4(bh[j], stb + 1 * TILE_B + offB[j] + so);
#pragma unroll
            for (int i = 0; i < 2; i++)
#pragma unroll
                for (int nf = 0; nf < 8; nf++)
                    mma16816(acc[i][nf], ah[i], &bh[nf >> 1][(nf & 1) * 2]);
        }
    }

    float* Co = kh ? CoB : CoA;
#pragma unroll
    for (int i = 0; i < 2; i++) {
        int r0 = bm + wm + i * 16 + (lane >> 2);
#pragma unroll
        for (int nf = 0; nf < 8; nf++) {
            int c = bn + wn + nf * 8 + (lane & 3) * 2;
            float b0 = kh ? 0.f : bias[c];
            float b1 = kh ? 0.f : bias[c + 1];
            if (r0 < NROI) {
                Co[(size_t)r0 * FDIM + c]     = acc[i][nf][0] + b0;
                Co[(size_t)r0 * FDIM + c + 1] = acc[i][nf][1] + b1;
            }
            if (r0 + 8 < NROI) {
                Co[(size_t)(r0 + 8) * FDIM + c]     = acc[i][nf][2] + b0;
                Co[(size_t)(r0 + 8) * FDIM + c + 1] = acc[i][nf][3] + b1;
            }
        }
    }
}
#define GSMEM (3 * 2 * TILE_B)    // 110592

// ---------------- head GEMM: 3-pass fp16 (Ah*Wh + Al*Wh + Ah*Wl) -----------
__device__ __forceinline__ void issue_stage4(
    const __half* __restrict__ Ah, const __half* __restrict__ Wh,
    const __half* __restrict__ Al, const __half* __restrict__ Wl,
    int K, int k0, uint32_t sbase, int tid)
{
    const __half* gs[4] = {Ah, Wh, Al, Wl};
#pragma unroll
    for (int t = 0; t < 4; t++) {
#pragma unroll
        for (int i = 0; i < 4; i++) {
            int u   = tid + i * 256;
            int row = u >> 3, seg = u & 7;
            const void* g = gs[t] + (size_t)row * K + k0 + seg * 8;
            uint32_t sm   = sbase + t * TILE_B + row * ROWB + seg * 16;
            CPA(sm, g);
        }
    }
}

__global__ __launch_bounds__(256, 1) void hmma_head(
    float* __restrict__ CoA, float* __restrict__ CoB)
{
    const int K = FDIM;
    const int khalf = FDIM / 2;
    const uint32_t STAGE = 4 * TILE_B;

    extern __shared__ char smem[];
    uint32_t sb = smem_u32(smem);

    int tid  = threadIdx.x;
    int wid  = tid >> 5, lane = tid & 31;
    int wm   = (wid & 3) * 32;
    int wn   = (wid >> 2) * 64;
    int bm   = blockIdx.y * 128;
    int bn   = blockIdx.x * 128;
    int kh   = blockIdx.z;

    const __half* Ah = g_A3hi + (size_t)bm * K + kh * khalf;
    const __half* Al = g_A3lo + (size_t)bm * K + kh * khalf;
    const __half* Wh = g_W3hi + (size_t)bn * K + kh * khalf;
    const __half* Wl = g_W3lo + (size_t)bn * K + kh * khalf;

    uint32_t offA[2], offB[4];
#pragma unroll
    for (int i = 0; i < 2; i++)
        offA[i] = (wm + i * 16 + (lane & 15)) * ROWB + ((lane >> 4) << 4);
#pragma unroll
    for (int j = 0; j < 4; j++)
        offB[j] = (wn + j * 16 + ((lane >> 4) << 3) + (lane & 7)) * ROWB
                + (((lane >> 3) & 1) << 4);

    float acc[2][8][4];
#pragma unroll
    for (int i = 0; i < 2; i++)
#pragma unroll
        for (int n = 0; n < 8; n++)
#pragma unroll
            for (int q = 0; q < 4; q++) acc[i][n][q] = 0.f;

    const int nch = khalf >> 6;   // 8

    issue_stage4(Ah, Wh, Al, Wl, K, 0, sb, tid);
    CPA_COMMIT();
    issue_stage4(Ah, Wh, Al, Wl, K, 64, sb + STAGE, tid);
    CPA_COMMIT();

    for (int k = 0; k < nch; k++) {
        if (k == nch - 1) { CPA_WAIT0(); } else { CPA_WAIT1(); }
        __syncthreads();

        if (k + 2 < nch) {
            issue_stage4(Ah, Wh, Al, Wl, K, (k + 2) << 6,
                         sb + ((k + 2) % 3) * STAGE, tid);
            CPA_COMMIT();
        }

        uint32_t stb = sb + (k % 3) * STAGE;
#pragma unroll
        for (int s = 0; s < 4; s++) {
            uint32_t so = s * 32;
            uint32_t ah[2][4], al[2][4], wh4[4][4], wl4[4][4];
#pragma unroll
            for (int i = 0; i < 2; i++) {
                ldm4(ah[i], stb + 0 * TILE_B + offA[i] + so);
                ldm4(al[i], stb + 2 * TILE_B + offA[i] + so);
            }
#pragma unroll
            for (int j = 0; j < 4; j++) {
                ldm4(wh4[j], stb + 1 * TILE_B + offB[j] + so);
                ldm4(wl4[j], stb + 3 * TILE_B + offB[j] + so);
            }
#pragma unroll
            for (int i = 0; i < 2; i++) {
#pragma unroll
                for (int nf = 0; nf < 8; nf++) {
                    const uint32_t* bph = &wh4[nf >> 1][(nf & 1) * 2];
                    const uint32_t* bpl = &wl4[nf >> 1][(nf & 1) * 2];
                    mma16816(acc[i][nf], ah[i], bph);
                    mma16816(acc[i][nf], al[i], bph);
                    mma16816(acc[i][nf], ah[i], bpl);
                }
            }
        }
    }

    float* Co = kh ? CoB : CoA;
#pragma unroll
    for (int i = 0; i < 2; i++) {
        int r0 = bm + wm + i * 16 + (lane >> 2);
#pragma unroll
        for (int nf = 0; nf < 8; nf++) {
            int c = bn + wn + nf * 8 + (lane & 3) * 2;
            if (r0 < NROI) {
                Co[(size_t)r0 * NPADW + c]     = acc[i][nf][0];
                Co[(size_t)r0 * NPADW + c + 1] = acc[i][nf][1];
            }
            if (r0 + 8 < NROI) {
                Co[(size_t)(r0 + 8) * NPADW + c]     = acc[i][nf][2];
                Co[(size_t)(r0 + 8) * NPADW + c + 1] = acc[i][nf][3];
            }
        }
    }
}
#define GSMEM4 (3 * 4 * TILE_B)    // 221184

// ---------------- BN stats: 20 chunks x 50 rows ----------------
__global__ __launch_bounds__(256) void bn_partial_kernel(int phase)
{
    int f  = blockIdx.x * 256 + threadIdx.x;
    int rc = blockIdx.y;
    int b  = blockIdx.z;
    size_t base = ((size_t)b * 1000 + rc * 50) * FDIM + f;

    const float* pa = (phase == 0 ? g_x1 : g_x2) + base;
    const float* pb = (phase == 0 ? g_x1b : g_x2b) + base;

    float s = 0.f, q = 0.f;
#pragma unroll 5
    for (int n = 0; n < 50; n++) {
        float v = pa[(size_t)n * FDIM] + pb[(size_t)n * FDIM];
        s += v; q += v * v;
    }
    int idx = (b * NCHK + rc) * FDIM + f;
    g_psum[idx] = s;
    g_psq[idx]  = q;
}

__global__ __launch_bounds__(256) void bn_final_kernel(int phase)
{
    float* mu   = (phase == 0) ? g_mu1   : g_mu2;
    float* rstd = (phase == 0) ? g_rstd1 : g_rstd2;
    int f = blockIdx.y * 256 + threadIdx.x;
    int b = blockIdx.x;

    float s = 0.f, q = 0.f;
#pragma unroll
    for (int rc = 0; rc < NCHK; rc++) {
        int idx = (b * NCHK + rc) * FDIM + f;
        s += g_psum[idx];
        q += g_psq[idx];
    }
    float m   = s * (1.0f / 1000.0f);
    float var = q * (1.0f / 1000.0f) - m * m;
    mu[b * FDIM + f]   = m;
    rstd[b * FDIM + f] = rsqrtf(var + 1e-5f);
}

// ---------------- BN+relu apply -> fp16 (hi [, lo]) ----------------
template<bool WRITE_LO>
__global__ __launch_bounds__(256) void bn_apply_kernel(
    const float* __restrict__ gam, const float* __restrict__ bet,
    const float* __restrict__ xa, const float* __restrict__ xb,
    const float* __restrict__ mu, const float* __restrict__ rstd,
    __half* __restrict__ hi, __half* __restrict__ lo)
{
    int i = blockIdx.x * 256 + threadIdx.x;
    if (i >= NROI * FDIM / 4) return;
    int e   = i * 4;
    int row = e >> 10;
    int b   = (row >= 1000);
    int kg  = e & 1023;

    float4 va  = *(const float4*)(xa + e);
    float4 vb  = *(const float4*)(xb + e);
    float4 g4  = *(const float4*)(gam + kg);
    float4 b4  = *(const float4*)(bet + kg);
    float4 mu4 = *(const float4*)(mu + b * FDIM + kg);
    float4 rs4 = *(const float4*)(rstd + b * FDIM + kg);
    float v0 = va.x + vb.x, v1 = va.y + vb.y, v2 = va.z + vb.z, v3 = va.w + vb.w;
    float o0 = fmaxf(g4.x * (v0 - mu4.x) * rs4.x + b4.x, 0.f);
    float o1 = fmaxf(g4.y * (v1 - mu4.y) * rs4.y + b4.y, 0.f);
    float o2 = fmaxf(g4.z * (v2 - mu4.z) * rs4.z + b4.z, 0.f);
    float o3 = fmaxf(g4.w * (v3 - mu4.w) * rs4.w + b4.w, 0.f);

    __half h0 = __float2half_rn(o0), h1 = __float2half_rn(o1);
    __half h2 = __float2half_rn(o2), h3 = __float2half_rn(o3);
    __half2* H = (__half2*)hi;
    H[i*2]   = __half2(h0, h1);
    H[i*2+1] = __half2(h2, h3);
    if (WRITE_LO) {
        __half2* L = (__half2*)lo;
        L[i*2]   = __half2(__float2half_rn(o0 - __half2float(h0)),
                           __float2half_rn(o1 - __half2float(h1)));
        L[i*2+1] = __half2(__float2half_rn(o2 - __half2float(h2)),
                           __float2half_rn(o3 - __half2float(h3)));
    }
}

// ---------------- finalize: bias + outputs + softmax ----------------
__global__ __launch_bounds__(256) void finalize_kernel(
    const float* __restrict__ bl, const float* __restrict__ bb,
    float* __restrict__ out)
{
    int tid  = threadIdx.x;
    int wid  = tid >> 5, lane = tid & 31;
    int m    = blockIdx.x * 8 + wid;

    const float* ha = g_h  + (size_t)m * NPADW;
    const float* hb = g_hb + (size_t)m * NPADW;

    float lgv[3] = {-1e30f, -1e30f, -1e30f};
    for (int i = lane, j = 0; i < NOUT; i += 32, j++) {
        float v = ha[i] + hb[i] + ((i < NCLS) ? bl[i] : bb[i - NCLS]);
        if (i < NCLS) {
            out[(size_t)m * NCLS + i] = v;
            lgv[j] = v;
        } else {
            out[324000 + (size_t)m * NBOX + (i - NCLS)] = v;
        }
    }

    float mx = fmaxf(lgv[0], fmaxf(lgv[1], lgv[2]));
#pragma unroll
    for (int off = 16; off; off >>= 1) mx = fmaxf(mx, __shfl_xor_sync(0xffffffffu, mx, off));
    float sum = 0.f;
#pragma unroll
    for (int j = 0; j < 3; j++)
        if (lgv[j] > -1e29f) sum += expf(lgv[j] - mx);
#pragma unroll
    for (int off = 16; off; off >>= 1) sum += __shfl_xor_sync(0xffffffffu, sum, off);
    float inv = 1.0f / sum;
#pragma unroll
    for (int j = 0; j < 3; j++) {
        int i = lane + j * 32;
        if (i < NCLS)
            out[162000 + (size_t)m * NCLS + i] = expf(lgv[j] - mx) * inv;
    }
}

// ---------------- launch ----------------
extern "C" void kernel_launch(void* const* d_in, const int* in_sizes, int n_in,
                              void* d_out, int out_size)
{
    const float* rois    = (const float*)d_in[0];
    const float* p2      = (const float*)d_in[1];
    const float* p3      = (const float*)d_in[2];
    const float* p4      = (const float*)d_in[3];
    const float* p5      = (const float*)d_in[4];
    const float* conv1_w = (const float*)d_in[5];
    const float* conv1_b = (const float*)d_in[6];
    const float* bn1_g   = (const float*)d_in[7];
    const float* bn1_b   = (const float*)d_in[8];
    const float* conv2_w = (const float*)d_in[9];
    const float* conv2_b = (const float*)d_in[10];
    const float* bn2_g   = (const float*)d_in[11];
    const float* bn2_b   = (const float*)d_in[12];
    const float* logitsW = (const float*)d_in[13];
    const float* logitsB = (const float*)d_in[14];
    const float* bboxW   = (const float*)d_in[15];
    const float* bboxB   = (const float*)d_in[16];
    float* out = (float*)d_out;

    // lazy one-time stream/event creation (first call is the non-capturing
    // correctness run; reused on the capture call)
    static cudaStream_t s2 = nullptr;
    static cudaEvent_t evFork = nullptr, evJoin = nullptr;
    if (!s2) {
        cudaStreamCreateWithFlags(&s2, cudaStreamNonBlocking);
        cudaEventCreateWithFlags(&evFork, cudaEventDisableTiming);
        cudaEventCreateWithFlags(&evJoin, cudaEventDisableTiming);
    }

    cudaFuncSetAttribute(hmma_gemm, cudaFuncAttributeMaxDynamicSharedMemorySize, GSMEM);
    cudaFuncSetAttribute(hmma_head, cudaFuncAttributeMaxDynamicSharedMemorySize, GSMEM4);

    __half *a1h, *b1h, *a2h, *b2h, *a3h, *a3l;
    float *x1, *x1b, *x2, *x2b, *hA, *hB;
    float *mu1, *rs1, *mu2, *rs2;
    cudaGetSymbolAddress((void**)&a1h, g_A1hi);
    cudaGetSymbolAddress((void**)&b1h, g_B1hi);
    cudaGetSymbolAddress((void**)&a2h, g_A2hi);
    cudaGetSymbolAddress((void**)&b2h, g_B2hi);
    cudaGetSymbolAddress((void**)&a3h, g_A3hi);
    cudaGetSymbolAddress((void**)&a3l, g_A3lo);
    cudaGetSymbolAddress((void**)&x1, g_x1);    cudaGetSymbolAddress((void**)&x1b, g_x1b);
    cudaGetSymbolAddress((void**)&x2, g_x2);    cudaGetSymbolAddress((void**)&x2b, g_x2b);
    cudaGetSymbolAddress((void**)&hA, g_h);     cudaGetSymbolAddress((void**)&hB, g_hb);
    cudaGetSymbolAddress((void**)&mu1, g_mu1);  cudaGetSymbolAddress((void**)&rs1, g_rstd1);
    cudaGetSymbolAddress((void**)&mu2, g_mu2);  cudaGetSymbolAddress((void**)&rs2, g_rstd2);

    const int n4_1 = FDIM * KDIM / 4;
    const int n4_2 = FDIM * FDIM / 4;
    const int napp = NROI * FDIM / 4;

    // fork: weight conversions on s2, concurrent with roi_align on stream 0
    cudaEventRecord(evFork, 0);
    cudaStreamWaitEvent(s2, evFork, 0);

    cvt_hi_kernel<<<(n4_1 + 255) / 256, 256, 0, s2>>>(conv1_w, b1h, n4_1);
    cvt_hi_kernel<<<(n4_2 + 255) / 256, 256, 0, s2>>>(conv2_w, b2h, n4_2);
    cvt_headw_kernel<<<NOUT, 256, 0, s2>>>(logitsW, bboxW);
    cudaEventRecord(evJoin, s2);

    roi_align_kernel<<<NROI, 256>>>(rois, p2, p3, p4, p5);

    // join before GEMM1
    cudaStreamWaitEvent(0, evJoin, 0);

    // GEMM1 (split-K x2, single-pass, 2 CTAs/SM)
    hmma_gemm<<<dim3(FDIM / 128, MPAD / 128, 2), 256, GSMEM>>>(
        a1h, b1h, conv1_b, x1, x1b, KDIM, KDIM / 2);

    // BN1
    bn_partial_kernel<<<dim3(4, NCHK, 2), 256>>>(0);
    bn_final_kernel<<<dim3(2, 4), 256>>>(0);
    bn_apply_kernel<false><<<(napp + 255) / 256, 256>>>(
        bn1_g, bn1_b, x1, x1b, mu1, rs1, a2h, nullptr);

    // GEMM2 (single-pass fp16, split-K x2)
    hmma_gemm<<<dim3(FDIM / 128, MPAD / 128, 2), 256, GSMEM>>>(
        a2h, b2h, conv2_b, x2, x2b, FDIM, FDIM / 2);

    // BN2 + apply -> A3 hi/lo
    bn_partial_kernel<<<dim3(4, NCHK, 2), 256>>>(1);
    bn_final_kernel<<<dim3(2, 4), 256>>>(1);
    bn_apply_kernel<true><<<(napp + 255) / 256, 256>>>(
        bn2_g, bn2_b, x2, x2b, mu2, rs2, a3h, a3l);

    // head GEMM (3-pass fp16, split-K x2) + finalize
    hmma_head<<<dim3(NPADW / 128, MPAD / 128, 2), 256, GSMEM4>>>(hA, hB);
    finalize_kernel<<<NROI / 8, 256>>>(logitsB, bboxB, out);
}